// round 3
// baseline (speedup 1.0000x reference)
#include <cuda_runtime.h>
#include <cuda_fp16.h>
#include <cstdint>

// ============================================================================
// Problem geometry
// ============================================================================
#define TOKENS 8192
#define D_IN   4096
#define D_OUT  4096

// GEMM tiling: block 128x256, warp tile 64x64 (8 warps as 2x4), BK=64
#define BM 128
#define BN 256
#define BK 64
#define STAGES 4
#define NIT (D_IN / BK)          // 64 k-iterations

#define ASTAGE_BYTES (BM * BK * 2)          // 16384
#define BSTAGE_BYTES (BN * BK * 2)          // 32768
#define STAGE_BYTES  (ASTAGE_BYTES + BSTAGE_BYTES)   // 49152
#define SMEM_TOTAL   (STAGES * STAGE_BYTES)          // 196608

// fp16 staging buffers (device globals: no allocation allowed anywhere)
__device__ __align__(1024) __half g_xh[(size_t)TOKENS * D_IN];
__device__ __align__(1024) __half g_wh[(size_t)D_OUT * D_IN];

// ============================================================================
// PTX helpers (base sm_100 only: cp.async + ldmatrix + mma.sync)
// ============================================================================
__device__ __forceinline__ uint32_t smem_to_u32(const void* p) {
    uint32_t a;
    asm("{ .reg .u64 t; cvta.to.shared.u64 t, %1; cvt.u32.u64 %0, t; }"
        : "=r"(a) : "l"(p));
    return a;
}

__device__ __forceinline__ void cp_async16(uint32_t smem, const void* gmem) {
    asm volatile("cp.async.cg.shared.global [%0], [%1], 16;"
                 :: "r"(smem), "l"(gmem) : "memory");
}
#define CP_COMMIT() asm volatile("cp.async.commit_group;" ::: "memory")
#define CP_WAIT(N)  asm volatile("cp.async.wait_group %0;" :: "n"(N) : "memory")

__device__ __forceinline__ void ldsm_x4(uint32_t* r, uint32_t addr) {
    asm volatile("ldmatrix.sync.aligned.m8n8.x4.shared.b16 {%0,%1,%2,%3}, [%4];"
                 : "=r"(r[0]), "=r"(r[1]), "=r"(r[2]), "=r"(r[3]) : "r"(addr));
}

__device__ __forceinline__ void mma16816(float* c, const uint32_t* a,
                                         uint32_t b0, uint32_t b1) {
    asm volatile(
        "mma.sync.aligned.m16n8k16.row.col.f32.f16.f16.f32 "
        "{%0,%1,%2,%3}, {%4,%5,%6,%7}, {%8,%9}, {%0,%1,%2,%3};"
        : "+f"(c[0]), "+f"(c[1]), "+f"(c[2]), "+f"(c[3])
        : "r"(a[0]), "r"(a[1]), "r"(a[2]), "r"(a[3]), "r"(b0), "r"(b1));
}

// ============================================================================
// Conversion kernels: fp32 -> fp16 (x), int32 -> fp16 (weight, exact)
// ============================================================================
__global__ void __launch_bounds__(256) cvt_x_kernel(const float4* __restrict__ x,
                                                    __half2* __restrict__ o, int n4) {
    int i = blockIdx.x * blockDim.x + threadIdx.x;
    if (i < n4) {
        float4 v = x[i];
        o[2 * i + 0] = __floats2half2_rn(v.x, v.y);
        o[2 * i + 1] = __floats2half2_rn(v.z, v.w);
    }
}

__global__ void __launch_bounds__(256) cvt_w_kernel(const int4* __restrict__ w,
                                                    __half2* __restrict__ o, int n4) {
    int i = blockIdx.x * blockDim.x + threadIdx.x;
    if (i < n4) {
        int4 v = w[i];
        o[2 * i + 0] = __halves2half2(__int2half_rn(v.x), __int2half_rn(v.y));
        o[2 * i + 1] = __halves2half2(__int2half_rn(v.z), __int2half_rn(v.w));
    }
}

// ============================================================================
// GEMM: out[m,n] = scales[n] * sum_k xh[m,k] * wh[n,k] + bias[n]
//   A = xh [TOKENS, D_IN] K-major,  B = wh [D_OUT, D_IN] K-major  (TN GEMM)
//   Smem layout: rows of 128B (8 x 16B chunks), chunk c of row r at (c ^ (r&7))
//   Register double-buffered ldmatrix over the 4 k16-slices of each stage.
// ============================================================================
__global__ void __launch_bounds__(256, 1) gemm_kernel(
    const __half* __restrict__ A,
    const __half* __restrict__ B,
    const float* __restrict__ scales,
    const float* __restrict__ bias,
    float* __restrict__ out) {
    extern __shared__ char smem[];
    const uint32_t sb = smem_to_u32(smem);
    const int tid = threadIdx.x;
    const int wid = tid >> 5;
    const int l = tid & 31;

    const int m0 = blockIdx.y * BM;
    const int n0 = blockIdx.x * BN;
    const int wm0 = (wid >> 2) * 64;     // warp row offset in tile (0/64)
    const int wn0 = (wid & 3) * 64;      // warp col offset in tile (0..192)

    // ---- stage loader: A 1024 + B 2048 16B chunks, swizzled ----
    auto load_stage = [&](int it, int st) {
        const int k0 = it * BK;
        const uint32_t sa = sb + st * STAGE_BYTES;
        const uint32_t sB = sa + ASTAGE_BYTES;
#pragma unroll
        for (int j = 0; j < 4; j++) {
            int q = tid + j * 256;
            int r = q >> 3, c = q & 7;
            uint32_t soff = (uint32_t)(r * 128 + ((c ^ (r & 7)) << 4));
            cp_async16(sa + soff, A + (size_t)(m0 + r) * D_IN + k0 + c * 8);
        }
#pragma unroll
        for (int j = 0; j < 8; j++) {
            int q = tid + j * 256;
            int r = q >> 3, c = q & 7;
            uint32_t soff = (uint32_t)(r * 128 + ((c ^ (r & 7)) << 4));
            cp_async16(sB + soff, B + (size_t)(n0 + r) * D_IN + k0 + c * 8);
        }
        CP_COMMIT();
    };

    // ---- prologue: fill STAGES-1 stages ----
#pragma unroll
    for (int s = 0; s < STAGES - 1; s++) load_stage(s, s);

    float acc[4][8][4];
#pragma unroll
    for (int mt = 0; mt < 4; mt++)
#pragma unroll
        for (int nt = 0; nt < 8; nt++)
#pragma unroll
            for (int q = 0; q < 4; q++) acc[mt][nt][q] = 0.0f;

    // ldmatrix lane addressing: lanes 0-15 -> rows, lanes 16-31 -> k-hi chunk
    const uint32_t a_lane_row = (uint32_t)((wm0 + (l & 15)) * 128);
    const uint32_t b_lane_row = (uint32_t)((wn0 + (l & 15)) * 128);
    const int chunk_hi = l >> 4;      // 0/1
    const int sw = l & 7;

    uint32_t af[2][16], bf[2][16];

    // fragment loader for k16-slice ks of the stage at (sa, sB)
    auto load_frags = [&](int buf, int ks, uint32_t sa, uint32_t sB) {
        const uint32_t koff = (uint32_t)(((2 * ks + chunk_hi) ^ sw) << 4);
#pragma unroll
        for (int mt = 0; mt < 4; mt++)
            ldsm_x4(&af[buf][mt * 4], sa + a_lane_row + mt * 2048 + koff);
#pragma unroll
        for (int nt = 0; nt < 4; nt++)
            ldsm_x4(&bf[buf][nt * 4], sB + b_lane_row + nt * 2048 + koff);
    };

    // ---- mainloop ----
    for (int it = 0; it < NIT; it++) {
        CP_WAIT(STAGES - 2);
        __syncthreads();

        // constant one commit per iteration so wait_group(STAGES-2) always
        // guarantees stage `it` is resident (no tail underflow)
        if (it + STAGES - 1 < NIT) {
            load_stage(it + STAGES - 1, (it + STAGES - 1) % STAGES);
        } else {
            CP_COMMIT();
        }

        const uint32_t sa = sb + (it % STAGES) * STAGE_BYTES;
        const uint32_t sB = sa + ASTAGE_BYTES;

        load_frags(0, 0, sa, sB);
#pragma unroll
        for (int ks = 0; ks < BK / 16; ks++) {
            const int cur = ks & 1;
            if (ks < BK / 16 - 1) load_frags(cur ^ 1, ks + 1, sa, sB);
#pragma unroll
            for (int mt = 0; mt < 4; mt++)
#pragma unroll
                for (int j = 0; j < 4; j++) {
                    // ldsm_x4 on B gives: r0=(n lo,k lo) r1=(n hi,k lo)
                    //                     r2=(n lo,k hi) r3=(n hi,k hi)
                    mma16816(acc[mt][2 * j + 0], &af[cur][mt * 4],
                             bf[cur][j * 4 + 0], bf[cur][j * 4 + 2]);
                    mma16816(acc[mt][2 * j + 1], &af[cur][mt * 4],
                             bf[cur][j * 4 + 1], bf[cur][j * 4 + 3]);
                }
        }
    }

    // ---- epilogue: fused dequant (scale/bias per output channel) ----
    const int m_base = m0 + wm0 + (l >> 2);
    const int n_base = n0 + wn0 + (l & 3) * 2;
    float s[8][2], b[8][2];
#pragma unroll
    for (int nt = 0; nt < 8; nt++) {
        const int n = n_base + nt * 8;
        s[nt][0] = __ldg(scales + n);
        s[nt][1] = __ldg(scales + n + 1);
        b[nt][0] = __ldg(bias + n);
        b[nt][1] = __ldg(bias + n + 1);
    }
#pragma unroll
    for (int mt = 0; mt < 4; mt++) {
        const int r0 = m_base + mt * 16;
#pragma unroll
        for (int nt = 0; nt < 8; nt++) {
            const int n = n_base + nt * 8;
            float2 v0 = make_float2(acc[mt][nt][0] * s[nt][0] + b[nt][0],
                                    acc[mt][nt][1] * s[nt][1] + b[nt][1]);
            float2 v1 = make_float2(acc[mt][nt][2] * s[nt][0] + b[nt][0],
                                    acc[mt][nt][3] * s[nt][1] + b[nt][1]);
            *(float2*)(out + (size_t)r0 * D_OUT + n) = v0;
            *(float2*)(out + (size_t)(r0 + 8) * D_OUT + n) = v1;
        }
    }
}

// ============================================================================
// Host launch
// ============================================================================
extern "C" void kernel_launch(void* const* d_in, const int* in_sizes, int n_in,
                              void* d_out, int out_size) {
    const float* x = (const float*)d_in[0];
    const int* wq = (const int*)d_in[1];
    const float* scales = (const float*)d_in[2];
    const float* bias = (const float*)d_in[3];
    float* out = (float*)d_out;

    void *xh = nullptr, *wh = nullptr;
    cudaGetSymbolAddress(&xh, g_xh);
    cudaGetSymbolAddress(&wh, g_wh);

    // Stage 1: dtype conversions (x: fp32->fp16, w: int32->fp16 exact)
    {
        int n4x = (TOKENS * D_IN) / 4;
        cvt_x_kernel<<<n4x / 256, 256>>>((const float4*)x, (__half2*)xh, n4x);
        int n4w = (D_OUT * D_IN) / 4;
        cvt_w_kernel<<<n4w / 256, 256>>>((const int4*)wq, (__half2*)wh, n4w);
    }

    // Stage 2: pipelined HMMA GEMM + fused dequant epilogue
    static bool attr_set = false;
    if (!attr_set) {
        cudaFuncSetAttribute(gemm_kernel,
                             cudaFuncAttributeMaxDynamicSharedMemorySize,
                             SMEM_TOTAL);
        attr_set = true;
    }
    dim3 grid(D_OUT / BN, TOKENS / BM);   // (16, 64), n fastest for L2 reuse
    gemm_kernel<<<grid, 256, SMEM_TOTAL>>>((const __half*)xh, (const __half*)wh,
                                           scales, bias, out);
}